// round 6
// baseline (speedup 1.0000x reference)
#include <cuda_runtime.h>
#include <cuda_fp16.h>
#include <math.h>
#include <stdint.h>

#define OLDV 50257
#define EMB_D 2048
#define T_TOK 32768
#define NNUM 4096
#define KDIM 8192
#define MGEMM 4096
#define NGEMM 2048

// fp16 scratch: hidden activations and W2
__device__ __align__(128) __half g_hh[(size_t)NNUM * KDIM];    // [4096, 8192] row-major
__device__ __align__(128) __half g_w2h[(size_t)KDIM * NGEMM];  // [8192, 2048] row-major

// ---------------------------------------------------------------------------
// helpers
// ---------------------------------------------------------------------------
__device__ __forceinline__ uint32_t s2u(const void* p) {
    uint32_t a;
    asm("{ .reg .u64 t; cvta.to.shared.u64 t, %1; cvt.u32.u64 %0, t; }"
        : "=r"(a) : "l"(p));
    return a;
}
__device__ __forceinline__ void ldsm_x4(uint32_t* r, uint32_t addr) {
    asm volatile("ldmatrix.sync.aligned.m8n8.x4.shared.b16 {%0,%1,%2,%3}, [%4];"
                 : "=r"(r[0]), "=r"(r[1]), "=r"(r[2]), "=r"(r[3]) : "r"(addr));
}
__device__ __forceinline__ void ldsm_x4_t(uint32_t* r, uint32_t addr) {
    asm volatile("ldmatrix.sync.aligned.m8n8.x4.trans.shared.b16 {%0,%1,%2,%3}, [%4];"
                 : "=r"(r[0]), "=r"(r[1]), "=r"(r[2]), "=r"(r[3]) : "r"(addr));
}
__device__ __forceinline__ void mma16816(float* c, const uint32_t* a, const uint32_t* b) {
    asm volatile("mma.sync.aligned.m16n8k16.row.col.f32.f16.f16.f32 "
                 "{%0,%1,%2,%3}, {%4,%5,%6,%7}, {%8,%9}, {%0,%1,%2,%3};"
                 : "+f"(c[0]), "+f"(c[1]), "+f"(c[2]), "+f"(c[3])
                 : "r"(a[0]), "r"(a[1]), "r"(a[2]), "r"(a[3]),
                   "r"(b[0]), "r"(b[1]));
}
#define CP16(s, g) asm volatile("cp.async.cg.shared.global [%0], [%1], 16;" :: "r"(s), "l"(g))
#define CP_COMMIT() asm volatile("cp.async.commit_group;" ::: "memory")
#define CP_WAIT(n)  asm volatile("cp.async.wait_group %0;" :: "n"(n) : "memory")

// ---------------------------------------------------------------------------
// Kernel 1: embedding gather/select
// ---------------------------------------------------------------------------
__global__ void gather_kernel(const int* __restrict__ ids,
                              const float* __restrict__ orig_emb,
                              const float* __restrict__ new_emb,
                              float* __restrict__ out) {
    int t = blockIdx.x;
    int id = ids[t];
    const float4* src = (id >= OLDV)
        ? (const float4*)(new_emb + (size_t)(id - OLDV) * EMB_D)
        : (const float4*)(orig_emb + (size_t)id * EMB_D);
    float4* dst = (float4*)(out + (size_t)t * EMB_D);
    int i = threadIdx.x;
    dst[i]       = src[i];
    dst[i + 256] = src[i + 256];
}

// ---------------------------------------------------------------------------
// Kernel 2: h = gelu_exact(feats @ W1 + b1) -> fp16
// ---------------------------------------------------------------------------
__device__ __forceinline__ float gelu_exact(float x) {
    return 0.5f * x * (1.0f + erff(x * 0.70710678118654752440f));
}

__global__ void hidden_kernel(const float* __restrict__ vals,
                              const int* __restrict__ units,
                              const float* __restrict__ unit_emb,
                              const float* __restrict__ W1,
                              const float* __restrict__ b1) {
    int i = blockIdx.y;
    float v = vals[i];
    int u = units[i];
    float e0 = unit_emb[u * 2];
    float e1 = unit_emb[u * 2 + 1];
    int k = (blockIdx.x * blockDim.x + threadIdx.x) * 8;
    __half2 h2[4];
    #pragma unroll
    for (int h = 0; h < 2; h++) {
        float4 w0 = *(const float4*)&W1[k + h * 4];
        float4 w1 = *(const float4*)&W1[KDIM + k + h * 4];
        float4 w2 = *(const float4*)&W1[2 * KDIM + k + h * 4];
        float4 bb = *(const float4*)&b1[k + h * 4];
        float r0 = gelu_exact(fmaf(v, w0.x, fmaf(e0, w1.x, fmaf(e1, w2.x, bb.x))));
        float r1 = gelu_exact(fmaf(v, w0.y, fmaf(e0, w1.y, fmaf(e1, w2.y, bb.y))));
        float r2 = gelu_exact(fmaf(v, w0.z, fmaf(e0, w1.z, fmaf(e1, w2.z, bb.z))));
        float r3 = gelu_exact(fmaf(v, w0.w, fmaf(e0, w1.w, fmaf(e1, w2.w, bb.w))));
        h2[h*2+0] = __floats2half2_rn(r0, r1);
        h2[h*2+1] = __floats2half2_rn(r2, r3);
    }
    *(uint4*)&g_hh[(size_t)i * KDIM + k] = *(uint4*)h2;
}

// ---------------------------------------------------------------------------
// Kernel 3: W2 fp32 -> fp16 (same row-major layout)
// ---------------------------------------------------------------------------
__global__ void w2h_kernel(const float* __restrict__ W2) {
    size_t idx = ((size_t)blockIdx.x * 256 + threadIdx.x) * 8;
    float4 a = *(const float4*)&W2[idx];
    float4 b = *(const float4*)&W2[idx + 4];
    __half2 h2[4];
    h2[0] = __floats2half2_rn(a.x, a.y);
    h2[1] = __floats2half2_rn(a.z, a.w);
    h2[2] = __floats2half2_rn(b.x, b.y);
    h2[3] = __floats2half2_rn(b.z, b.w);
    *(uint4*)&g_w2h[idx] = *(uint4*)h2;
}

// ---------------------------------------------------------------------------
// Kernel 4: fp16 tensor-core GEMM (mma.sync) + scatter-add epilogue
// 128x128x64 tiles, 8 warps (4x2, warp 32x64), 3-stage cp.async, 4 ks/barrier.
// A stage: 128 rows x 128B (8 chunks, xor-swizzle ch^(row&7))
// B stage: 64 rows x 256B (16 chunks, xor-swizzle ch^(k&7))
// ---------------------------------------------------------------------------
#define BM 128
#define BN 128
#define BK 64
#define NSTAGE 3
#define STG_B 32768            // per-stage bytes (A 16K + B 16K)
#define SMEM_TOTAL (NSTAGE * STG_B)
#define NIT (KDIM / BK)        // 128

__global__ __launch_bounds__(256, 2)
void gemm_kernel(const float* __restrict__ b2,
                 const int* __restrict__ pos,
                 float* __restrict__ out) {
    extern __shared__ char smem[];
    const uint32_t sbase = s2u(smem);
    const int tid = threadIdx.x;
    const int lane = tid & 31;
    const int wid = tid >> 5;
    const int warp_m = wid >> 1;      // 0..3 (32 rows each)
    const int warp_n = wid & 1;       // 0..1 (64 cols each)
    const int m0 = blockIdx.y * BM;
    const int n0 = blockIdx.x * BN;

    const __half* Ag = g_hh + (size_t)m0 * KDIM;
    const __half* Bg = g_w2h + n0;

    // cp.async mapping:
    // A: 128 rows x 8 chunks(16B); thread t -> row t>>1, chunks (t&1)*4 + j
    // B: 64 rows x 16 chunks;      thread t -> row t>>2, chunks (t&3)*4 + j
    const int ar = tid >> 1;
    const int ac0 = (tid & 1) * 4;
    const int bk = tid >> 2;
    const int bc0 = (tid & 3) * 4;
    uint32_t a_sm[4], b_sm[4];
    #pragma unroll
    for (int j = 0; j < 4; j++) {
        a_sm[j] = sbase + ar * 128 + (((ac0 + j) ^ (ar & 7)) * 16);
        b_sm[j] = sbase + 16384 + bk * 256 + (((bc0 + j) ^ (bk & 7)) * 16);
    }
    const __half* agp = Ag + (size_t)ar * KDIM + ac0 * 8;
    const __half* bgp0 = Bg + (size_t)bk * NGEMM + bc0 * 8;

    // prologue: stages 0,1
    #pragma unroll
    for (int s = 0; s < NSTAGE - 1; s++) {
        const uint32_t so = s * STG_B;
        const __half* ag = agp + s * BK;
        const __half* bg = bgp0 + (size_t)(s * BK) * NGEMM;
        #pragma unroll
        for (int j = 0; j < 4; j++) {
            CP16(a_sm[j] + so, ag + j * 8);
            CP16(b_sm[j] + so, bg + j * 8);
        }
        CP_COMMIT();
    }

    float acc[2][8][4];
    #pragma unroll
    for (int mt = 0; mt < 2; mt++)
        #pragma unroll
        for (int nt = 0; nt < 8; nt++)
            #pragma unroll
            for (int j = 0; j < 4; j++) acc[mt][nt][j] = 0.0f;

    // fragment smem offset bases (relative to stage base)
    const int hi = lane >> 4;
    const int lo = lane & 15;
    const int arow0 = warp_m * 32 + lo;          // mt=0 row; mt=1 = +16
    const int r7 = arow0 & 7;                     // same for both mt
    const uint32_t abase0 = (uint32_t)(arow0 * 128);
    const uint32_t abase1 = abase0 + 16 * 128;
    uint32_t bbase[4];
    #pragma unroll
    for (int np = 0; np < 4; np++)
        bbase[np] = 16384 + lo * 256 +
                    (((warp_n * 8 + np * 2 + hi) ^ (lo & 7)) * 16);

    int rd = 0, wr = NSTAGE - 1;

    #pragma unroll 1
    for (int kt = 0; kt < NIT; kt++) {
        CP_WAIT(NSTAGE - 2);
        __syncthreads();

        // issue loads for tile kt+2 into slot wr
        if (kt + NSTAGE - 1 < NIT) {
            const int s = kt + NSTAGE - 1;
            const uint32_t so = wr * STG_B;
            const __half* ag = agp + s * BK;
            const __half* bg = bgp0 + (size_t)(s * BK) * NGEMM;
            #pragma unroll
            for (int j = 0; j < 4; j++) {
                CP16(a_sm[j] + so, ag + j * 8);
                CP16(b_sm[j] + so, bg + j * 8);
            }
        }
        CP_COMMIT();

        const uint32_t st = sbase + rd * STG_B;
        #pragma unroll
        for (int ks = 0; ks < 4; ks++) {
            uint32_t a[2][4], b[4][4];
            const uint32_t chA = (uint32_t)(((ks * 2 + hi) ^ r7) * 16);
            ldsm_x4(a[0], st + abase0 + chA);
            ldsm_x4(a[1], st + abase1 + chA);
            #pragma unroll
            for (int np = 0; np < 4; np++)
                ldsm_x4_t(b[np], st + bbase[np] + ks * 4096);
            #pragma unroll
            for (int mt = 0; mt < 2; mt++) {
                #pragma unroll
                for (int np = 0; np < 4; np++) {
                    mma16816(acc[mt][np * 2],     a[mt], &b[np][0]);
                    mma16816(acc[mt][np * 2 + 1], a[mt], &b[np][2]);
                }
            }
        }
        rd = (rd == NSTAGE - 1) ? 0 : rd + 1;
        wr = (wr == NSTAGE - 1) ? 0 : wr + 1;
    }

    // epilogue: scatter-add (+ b2) into out rows pos[m]
    #pragma unroll
    for (int mt = 0; mt < 2; mt++) {
        const int rbase = m0 + warp_m * 32 + mt * 16 + (lane >> 2);
        const int p0 = pos[rbase];
        const int p1 = pos[rbase + 8];
        const int cbase = n0 + warp_n * 64 + (lane & 3) * 2;
        float* o0 = out + (size_t)p0 * EMB_D + cbase;
        float* o1 = out + (size_t)p1 * EMB_D + cbase;
        const float* bb = b2 + cbase;
        #pragma unroll
        for (int nt = 0; nt < 8; nt++) {
            float bx = bb[nt * 8], by = bb[nt * 8 + 1];
            float2 v0 = *(float2*)(o0 + nt * 8);
            v0.x += acc[mt][nt][0] + bx;
            v0.y += acc[mt][nt][1] + by;
            *(float2*)(o0 + nt * 8) = v0;
            float2 v1 = *(float2*)(o1 + nt * 8);
            v1.x += acc[mt][nt][2] + bx;
            v1.y += acc[mt][nt][3] + by;
            *(float2*)(o1 + nt * 8) = v1;
        }
    }
}

// ---------------------------------------------------------------------------
extern "C" void kernel_launch(void* const* d_in, const int* in_sizes, int n_in,
                              void* d_out, int out_size) {
    const int*   input_ids  = (const int*)d_in[0];
    const int*   num_pos    = (const int*)d_in[1];
    const float* num_values = (const float*)d_in[2];
    const int*   num_units  = (const int*)d_in[3];
    const float* orig_emb   = (const float*)d_in[4];
    const float* new_emb    = (const float*)d_in[5];
    const float* unit_emb   = (const float*)d_in[6];
    const float* W1         = (const float*)d_in[7];
    const float* b1         = (const float*)d_in[8];
    const float* W2         = (const float*)d_in[9];
    const float* b2         = (const float*)d_in[10];
    float* out = (float*)d_out;

    cudaFuncSetAttribute(gemm_kernel,
                         cudaFuncAttributeMaxDynamicSharedMemorySize, SMEM_TOTAL);

    // 1) gather/select embeddings
    gather_kernel<<<T_TOK, 256>>>(input_ids, orig_emb, new_emb, out);

    // 2) hidden activations -> fp16
    dim3 hgrid(KDIM / (256 * 8), NNUM);
    hidden_kernel<<<hgrid, 256>>>(num_values, num_units, unit_emb, W1, b1);

    // 3) W2 -> fp16
    w2h_kernel<<<(KDIM * NGEMM) / (256 * 8), 256>>>(W2);

    // 4) tensor-core GEMM + scatter-add
    dim3 ggrid(NGEMM / BN, MGEMM / BM);
    gemm_kernel<<<ggrid, 256, SMEM_TOTAL>>>(b2, num_pos, out);
}

// round 9
// speedup vs baseline: 1.3076x; 1.3076x over previous
#include <cuda_runtime.h>
#include <cuda_fp16.h>
#include <math.h>
#include <stdint.h>

#define OLDV 50257
#define FINV 52257
#define EMB_D 2048
#define T_TOK 32768
#define NNUM 4096
#define KDIM 8192
#define MGEMM 4096
#define NGEMM 2048

// fp16 scratch: hidden activations and W2
__device__ __align__(128) __half g_hh[(size_t)NNUM * KDIM];    // [4096, 8192] row-major
__device__ __align__(128) __half g_w2h[(size_t)KDIM * NGEMM];  // [8192, 2048] row-major

// ---------------------------------------------------------------------------
// helpers
// ---------------------------------------------------------------------------
__device__ __forceinline__ uint32_t s2u(const void* p) {
    uint32_t a;
    asm("{ .reg .u64 t; cvta.to.shared.u64 t, %1; cvt.u32.u64 %0, t; }"
        : "=r"(a) : "l"(p));
    return a;
}
__device__ __forceinline__ void ldsm_x4(uint32_t* r, uint32_t addr) {
    asm volatile("ldmatrix.sync.aligned.m8n8.x4.shared.b16 {%0,%1,%2,%3}, [%4];"
                 : "=r"(r[0]), "=r"(r[1]), "=r"(r[2]), "=r"(r[3]) : "r"(addr));
}
__device__ __forceinline__ void ldsm_x4_t(uint32_t* r, uint32_t addr) {
    asm volatile("ldmatrix.sync.aligned.m8n8.x4.trans.shared.b16 {%0,%1,%2,%3}, [%4];"
                 : "=r"(r[0]), "=r"(r[1]), "=r"(r[2]), "=r"(r[3]) : "r"(addr));
}
__device__ __forceinline__ void mma16816(float* c, const uint32_t* a, const uint32_t* b) {
    asm volatile("mma.sync.aligned.m16n8k16.row.col.f32.f16.f16.f32 "
                 "{%0,%1,%2,%3}, {%4,%5,%6,%7}, {%8,%9}, {%0,%1,%2,%3};"
                 : "+f"(c[0]), "+f"(c[1]), "+f"(c[2]), "+f"(c[3])
                 : "r"(a[0]), "r"(a[1]), "r"(a[2]), "r"(a[3]),
                   "r"(b[0]), "r"(b[1]));
}
#define CP16(s, g) asm volatile("cp.async.cg.shared.global [%0], [%1], 16;" :: "r"(s), "l"(g))
#define CP_COMMIT() asm volatile("cp.async.commit_group;" ::: "memory")
#define CP_WAIT(n)  asm volatile("cp.async.wait_group %0;" :: "n"(n) : "memory")

__device__ __forceinline__ float gelu_exact(float x) {
    return 0.5f * x * (1.0f + erff(x * 0.70710678118654752440f));
}

// ---------------------------------------------------------------------------
// Kernel 1 (prep): blocks 0..16383 -> hidden activations; rest -> W2 fp32->fp16
// ---------------------------------------------------------------------------
#define HID_BLOCKS 16384                       // (KDIM/(256*8)) * NNUM = 4 * 4096
#define W2H_BLOCKS ((KDIM * NGEMM) / (256 * 8))  // 8192
__global__ void prep_kernel(const float* __restrict__ vals,
                            const int* __restrict__ units,
                            const float* __restrict__ unit_emb,
                            const float* __restrict__ W1,
                            const float* __restrict__ b1,
                            const float* __restrict__ W2) {
    int b = blockIdx.x;
    if (b < HID_BLOCKS) {
        int i = b >> 2;
        float v = vals[i];
        int u = units[i];
        float e0 = unit_emb[u * 2];
        float e1 = unit_emb[u * 2 + 1];
        int k = ((b & 3) * 256 + threadIdx.x) * 8;
        __half2 h2[4];
        #pragma unroll
        for (int h = 0; h < 2; h++) {
            float4 w0 = *(const float4*)&W1[k + h * 4];
            float4 w1 = *(const float4*)&W1[KDIM + k + h * 4];
            float4 w2 = *(const float4*)&W1[2 * KDIM + k + h * 4];
            float4 bb = *(const float4*)&b1[k + h * 4];
            float r0 = gelu_exact(fmaf(v, w0.x, fmaf(e0, w1.x, fmaf(e1, w2.x, bb.x))));
            float r1 = gelu_exact(fmaf(v, w0.y, fmaf(e0, w1.y, fmaf(e1, w2.y, bb.y))));
            float r2 = gelu_exact(fmaf(v, w0.z, fmaf(e0, w1.z, fmaf(e1, w2.z, bb.z))));
            float r3 = gelu_exact(fmaf(v, w0.w, fmaf(e0, w1.w, fmaf(e1, w2.w, bb.w))));
            h2[h*2+0] = __floats2half2_rn(r0, r1);
            h2[h*2+1] = __floats2half2_rn(r2, r3);
        }
        *(uint4*)&g_hh[(size_t)i * KDIM + k] = *(uint4*)h2;
    } else {
        size_t idx = ((size_t)(b - HID_BLOCKS) * 256 + threadIdx.x) * 8;
        float4 a = *(const float4*)&W2[idx];
        float4 c = *(const float4*)&W2[idx + 4];
        __half2 h2[4];
        h2[0] = __floats2half2_rn(a.x, a.y);
        h2[1] = __floats2half2_rn(a.z, a.w);
        h2[2] = __floats2half2_rn(c.x, c.y);
        h2[3] = __floats2half2_rn(c.z, c.w);
        *(uint4*)&g_w2h[idx] = *(uint4*)h2;
    }
}

// ---------------------------------------------------------------------------
// Kernel 2 (fused): blocks 0..511 = fp16 mma.sync GEMM (R5 config);
// blocks 512.. = gather (8 tokens each, SKIPPING numeric rows id>=FIN).
// GEMM epilogue writes numeric rows fully: new_emb[id-OLD] + acc + b2.
// ---------------------------------------------------------------------------
#define BM 128
#define BN 128
#define BK 32
#define NSTAGE 4
#define STG_B 16384
#define SMEM_TOTAL (NSTAGE * STG_B)
#define NIT (KDIM / BK)        // 256
#define GEMM_BLOCKS ((MGEMM / BM) * (NGEMM / BN))   // 512
#define TOK_PER_BLK 8
#define GATHER_BLOCKS (T_TOK / TOK_PER_BLK)         // 4096

__global__ __launch_bounds__(256, 2)
void fused_kernel(const int* __restrict__ ids,
                  const float* __restrict__ orig_emb,
                  const float* __restrict__ new_emb,
                  const float* __restrict__ b2,
                  const int* __restrict__ pos,
                  float* __restrict__ out) {
    if (blockIdx.x >= GEMM_BLOCKS) {
        // ----- gather part -----
        const int tbase = (blockIdx.x - GEMM_BLOCKS) * TOK_PER_BLK;
        const int i = threadIdx.x;
        #pragma unroll
        for (int tk = 0; tk < TOK_PER_BLK; tk++) {
            const int t = tbase + tk;
            const int id = ids[t];
            if (id >= FINV) continue;            // numeric rows written by GEMM
            const float4* src = (id >= OLDV)
                ? (const float4*)(new_emb + (size_t)(id - OLDV) * EMB_D)
                : (const float4*)(orig_emb + (size_t)id * EMB_D);
            float4* dst = (float4*)(out + (size_t)t * EMB_D);
            dst[i]       = src[i];
            dst[i + 256] = src[i + 256];
        }
        return;
    }

    // ----- GEMM part (R5 mainloop) -----
    extern __shared__ char smem[];
    const uint32_t sbase = s2u(smem);
    const int tid = threadIdx.x;
    const int lane = tid & 31;
    const int wid = tid >> 5;
    const int warp_m = wid >> 1;
    const int warp_n = wid & 1;
    const int m0 = (blockIdx.x >> 4) * BM;       // 32 M-tiles
    const int n0 = (blockIdx.x & 15) * BN;       // 16 N-tiles

    const __half* Ag = g_hh + (size_t)m0 * KDIM;
    const __half* Bg = g_w2h + n0;

    const int ar = tid >> 1;
    const int ac0 = (tid & 1) * 2;
    const int bk = tid >> 3;
    const int bc0 = (tid & 7) * 2;
    const uint32_t a_s0 = sbase + ar * 64 + (((ac0)     ^ ((ar >> 1) & 3)) * 16);
    const uint32_t a_s1 = sbase + ar * 64 + (((ac0 + 1) ^ ((ar >> 1) & 3)) * 16);
    const uint32_t b_s0 = sbase + 8192 + bk * 256 + (((bc0)     ^ (bk & 7)) * 16);
    const uint32_t b_s1 = sbase + 8192 + bk * 256 + (((bc0 + 1) ^ (bk & 7)) * 16);
    const __half* agp = Ag + (size_t)ar * KDIM;

    #pragma unroll
    for (int s = 0; s < NSTAGE - 1; s++) {
        const uint32_t so = s * STG_B;
        CP16(a_s0 + so, agp + s * BK + ac0 * 8);
        CP16(a_s1 + so, agp + s * BK + (ac0 + 1) * 8);
        const __half* bgp = Bg + (size_t)(s * BK + bk) * NGEMM;
        CP16(b_s0 + so, bgp + bc0 * 8);
        CP16(b_s1 + so, bgp + (bc0 + 1) * 8);
        CP_COMMIT();
    }

    float acc[2][8][4];
    #pragma unroll
    for (int mt = 0; mt < 2; mt++)
        #pragma unroll
        for (int nt = 0; nt < 8; nt++)
            #pragma unroll
            for (int j = 0; j < 4; j++) acc[mt][nt][j] = 0.0f;

    uint32_t a_off[2][2], b_off[2][4];
    #pragma unroll
    for (int ks = 0; ks < 2; ks++) {
        #pragma unroll
        for (int mt = 0; mt < 2; mt++) {
            int row = warp_m * 32 + mt * 16 + (lane & 15);
            int ch = ks * 2 + (lane >> 4);
            a_off[ks][mt] = row * 64 + ((ch ^ ((row >> 1) & 3)) * 16);
        }
        #pragma unroll
        for (int np = 0; np < 4; np++) {
            int k = ks * 16 + (lane & 15);
            int ch = warp_n * 8 + np * 2 + (lane >> 4);
            b_off[ks][np] = 8192 + k * 256 + ((ch ^ (k & 7)) * 16);
        }
    }

    #pragma unroll 1
    for (int kt = 0; kt < NIT; kt++) {
        CP_WAIT(NSTAGE - 2);
        __syncthreads();

        if (kt + NSTAGE - 1 < NIT) {
            const int s = kt + NSTAGE - 1;
            const uint32_t so = (s & 3) * STG_B;
            CP16(a_s0 + so, agp + s * BK + ac0 * 8);
            CP16(a_s1 + so, agp + s * BK + (ac0 + 1) * 8);
            const __half* bgp = Bg + (size_t)(s * BK + bk) * NGEMM;
            CP16(b_s0 + so, bgp + bc0 * 8);
            CP16(b_s1 + so, bgp + (bc0 + 1) * 8);
        }
        CP_COMMIT();

        const uint32_t st = sbase + (kt & 3) * STG_B;
        #pragma unroll
        for (int ks = 0; ks < 2; ks++) {
            uint32_t a[2][4], b[4][4];
            #pragma unroll
            for (int mt = 0; mt < 2; mt++) ldsm_x4(a[mt], st + a_off[ks][mt]);
            #pragma unroll
            for (int np = 0; np < 4; np++) ldsm_x4_t(b[np], st + b_off[ks][np]);
            #pragma unroll
            for (int mt = 0; mt < 2; mt++) {
                #pragma unroll
                for (int np = 0; np < 4; np++) {
                    mma16816(acc[mt][np * 2],     a[mt], &b[np][0]);
                    mma16816(acc[mt][np * 2 + 1], a[mt], &b[np][2]);
                }
            }
        }
    }

    // epilogue: numeric rows written in full (no dependence on gather):
    // out[p, c] = new_emb[id(p)-OLDV, c] + acc + b2[c]
    #pragma unroll
    for (int mt = 0; mt < 2; mt++) {
        const int rbase = m0 + warp_m * 32 + mt * 16 + (lane >> 2);
        const int p0 = pos[rbase];
        const int p1 = pos[rbase + 8];
        const int cbase = n0 + warp_n * 64 + (lane & 3) * 2;
        const float* ne0 = new_emb + (size_t)(ids[p0] - OLDV) * EMB_D + cbase;
        const float* ne1 = new_emb + (size_t)(ids[p1] - OLDV) * EMB_D + cbase;
        float* o0 = out + (size_t)p0 * EMB_D + cbase;
        float* o1 = out + (size_t)p1 * EMB_D + cbase;
        const float* bb = b2 + cbase;
        #pragma unroll
        for (int nt = 0; nt < 8; nt++) {
            float bx = bb[nt * 8], by = bb[nt * 8 + 1];
            float2 e0 = *(const float2*)(ne0 + nt * 8);
            float2 v0;
            v0.x = e0.x + acc[mt][nt][0] + bx;
            v0.y = e0.y + acc[mt][nt][1] + by;
            *(float2*)(o0 + nt * 8) = v0;
            float2 e1 = *(const float2*)(ne1 + nt * 8);
            float2 v1;
            v1.x = e1.x + acc[mt][nt][2] + bx;
            v1.y = e1.y + acc[mt][nt][3] + by;
            *(float2*)(o1 + nt * 8) = v1;
        }
    }
}

// ---------------------------------------------------------------------------
extern "C" void kernel_launch(void* const* d_in, const int* in_sizes, int n_in,
                              void* d_out, int out_size) {
    const int*   input_ids  = (const int*)d_in[0];
    const int*   num_pos    = (const int*)d_in[1];
    const float* num_values = (const float*)d_in[2];
    const int*   num_units  = (const int*)d_in[3];
    const float* orig_emb   = (const float*)d_in[4];
    const float* new_emb    = (const float*)d_in[5];
    const float* unit_emb   = (const float*)d_in[6];
    const float* W1         = (const float*)d_in[7];
    const float* b1         = (const float*)d_in[8];
    const float* W2         = (const float*)d_in[9];
    const float* b2         = (const float*)d_in[10];
    float* out = (float*)d_out;

    cudaFuncSetAttribute(fused_kernel,
                         cudaFuncAttributeMaxDynamicSharedMemorySize, SMEM_TOTAL);

    // 1) hidden activations + W2 conversion (one launch)
    prep_kernel<<<HID_BLOCKS + W2H_BLOCKS, 256>>>(num_values, num_units, unit_emb,
                                                  W1, b1, W2);

    // 2) fused GEMM + gather (gather backfills GEMM tail wave)
    fused_kernel<<<GEMM_BLOCKS + GATHER_BLOCKS, 256, SMEM_TOTAL>>>(
        input_ids, orig_emb, new_emb, b2, num_pos, out);
}